// round 1
// baseline (speedup 1.0000x reference)
#include <cuda_runtime.h>
#include <stdint.h>

// XNOR binarized linear: y[n,o] = (256 - 2*popc(xbits[n] ^ wbits[o])) * scale[o]
// N = 262144 rows, IN = OUT = 256.

constexpr int NROWS = 262144;
constexpr int DIM   = 256;   // IN == OUT
constexpr int WPR   = 8;     // 32-bit words per packed row (256/32)
constexpr int TILE  = 256;   // rows per block tile

// Packed weight bits (8 KB) — scratch via __device__ global (no allocs allowed).
__device__ uint32_t g_wbits[DIM * WPR];

// ---------------------------------------------------------------------------
// Pre-kernel: pack weight sign bits. One warp per output row.
// Bit order convention (shared with the x pack): word (c*4+s), bit l
// corresponds to element c*128 + 4*l + s. Order is arbitrary but must match.
// ---------------------------------------------------------------------------
__global__ void pack_w_kernel(const float* __restrict__ w) {
    int warp = (blockIdx.x * blockDim.x + threadIdx.x) >> 5;
    int lane = threadIdx.x & 31;
    if (warp >= DIM) return;
    const float4* row = reinterpret_cast<const float4*>(w) + (size_t)warp * (DIM / 4);
#pragma unroll
    for (int c = 0; c < 2; ++c) {
        float4 v = row[c * 32 + lane];
        uint32_t m0 = __ballot_sync(0xFFFFFFFFu, v.x < 0.0f);
        uint32_t m1 = __ballot_sync(0xFFFFFFFFu, v.y < 0.0f);
        uint32_t m2 = __ballot_sync(0xFFFFFFFFu, v.z < 0.0f);
        uint32_t m3 = __ballot_sync(0xFFFFFFFFu, v.w < 0.0f);
        if (lane == 0) {
            *reinterpret_cast<uint4*>(&g_wbits[warp * WPR + c * 4]) =
                make_uint4(m0, m1, m2, m3);
        }
    }
}

// ---------------------------------------------------------------------------
// Main kernel.
// Phase A: each of 8 warps packs 32 rows of x into shared (ballot packing).
// Phase B: warp w owns outputs o = 32w+lane (weights + scale in registers),
//          loops over the 256 shared rows; stores are 128B-coalesced per warp.
// ---------------------------------------------------------------------------
__global__ void __launch_bounds__(256)
xnor_main_kernel(const float* __restrict__ x,
                 const float* __restrict__ scale,
                 float* __restrict__ out) {
    __shared__ uint4 xb[TILE][2];   // 256 rows x 8 packed words = 8 KB

    const int tid  = threadIdx.x;
    const int warp = tid >> 5;
    const int lane = tid & 31;

    // Per-lane output column + its packed weights / scale (live in registers).
    const int o = warp * 32 + lane;
    const uint4 wa = *reinterpret_cast<const uint4*>(&g_wbits[o * WPR]);
    const uint4 wb = *reinterpret_cast<const uint4*>(&g_wbits[o * WPR + 4]);
    const float s  = scale[o];

    const int ntiles = NROWS / TILE;
    for (int tile = blockIdx.x; tile < ntiles; tile += gridDim.x) {
        const int rowbase = tile * TILE;

        // ----- Phase A: pack x rows into shared -----
        const float4* xt = reinterpret_cast<const float4*>(x) +
                           (size_t)rowbase * (DIM / 4);
#pragma unroll 4
        for (int k = 0; k < 32; ++k) {
            const int r = warp * 32 + k;
            const float4* row = xt + (size_t)r * (DIM / 4);
#pragma unroll
            for (int c = 0; c < 2; ++c) {
                float4 v = row[c * 32 + lane];
                uint32_t m0 = __ballot_sync(0xFFFFFFFFu, v.x < 0.0f);
                uint32_t m1 = __ballot_sync(0xFFFFFFFFu, v.y < 0.0f);
                uint32_t m2 = __ballot_sync(0xFFFFFFFFu, v.z < 0.0f);
                uint32_t m3 = __ballot_sync(0xFFFFFFFFu, v.w < 0.0f);
                if (lane == 0) xb[r][c] = make_uint4(m0, m1, m2, m3);
            }
        }
        __syncthreads();

        // ----- Phase B: popc(xor) over all tile rows -----
        float* ocol = out + (size_t)rowbase * DIM + o;
#pragma unroll 4
        for (int r = 0; r < TILE; ++r) {
            uint4 a = xb[r][0];   // LDS.128 broadcast
            uint4 b = xb[r][1];
            int acc = __popc(a.x ^ wa.x) + __popc(a.y ^ wa.y) +
                      __popc(a.z ^ wa.z) + __popc(a.w ^ wa.w) +
                      __popc(b.x ^ wb.x) + __popc(b.y ^ wb.y) +
                      __popc(b.z ^ wb.z) + __popc(b.w ^ wb.w);
            ocol[(size_t)r * DIM] = (float)(DIM - 2 * acc) * s;
        }
        __syncthreads();   // protect xb before next tile's Phase A
    }
}

// ---------------------------------------------------------------------------
// kernel_launch: d_in[0]=x [N,256] f32, d_in[1]=weight [256,256] f32,
//                d_in[2]=scale [1,256] f32; d_out = y [N,256] f32.
// ---------------------------------------------------------------------------
extern "C" void kernel_launch(void* const* d_in, const int* in_sizes, int n_in,
                              void* d_out, int out_size) {
    const float* x      = (const float*)d_in[0];
    const float* weight = (const float*)d_in[1];
    const float* scale  = (const float*)d_in[2];
    float* out          = (float*)d_out;
    (void)in_sizes; (void)n_in; (void)out_size;

    // Pack weights (256 warps).
    pack_w_kernel<<<32, 256>>>(weight);

    // Main kernel: 1024 tiles of 256 rows.
    xnor_main_kernel<<<NROWS / TILE, 256>>>(x, scale, out);
}